// round 4
// baseline (speedup 1.0000x reference)
#include <cuda_runtime.h>
#include <math.h>

#define BB 128
#define SSN 256
#define TTN 256
#define UU 512
#define GG 2048
#define TI_T 257

__device__ float g_xproj[(size_t)TTN * BB * GG];
__device__ float g_h[(size_t)(TTN + 1) * BB * UU];
__device__ float g_c[(size_t)BB * UU];
__device__ float g_w[(size_t)TTN * BB * UU];
__device__ float g_zpart[(size_t)8 * BB * GG];

__global__ void init_kernel(const float* __restrict__ h0, const float* __restrict__ c0) {
    int i = blockIdx.x * blockDim.x + threadIdx.x;
    g_h[i] = h0[i];
    g_c[i] = c0[i];
}

// Shared 128x128 GEMM body: A staged transposed [8][128], B [8][128], 8x8 micro.
#define GEMM_DECLS \
    __shared__ float sA[8][128]; \
    __shared__ float sB[8][128]; \
    const int tid = threadIdx.x; \
    const int ty = tid >> 4, tx = tid & 15; \
    const int arow = tid & 127, akf = tid >> 7; \
    const int bk = tid >> 5, bn4 = tid & 31; \
    float acc[8][8]; \
    _Pragma("unroll") for (int i = 0; i < 8; i++) \
    _Pragma("unroll") for (int j = 0; j < 8; j++) acc[i][j] = 0.f;

#define GEMM_STEP(AV, BV) { \
    float4 av = (AV); float4 bv = (BV); \
    __syncthreads(); \
    sA[akf*4+0][arow] = av.x; sA[akf*4+1][arow] = av.y; \
    sA[akf*4+2][arow] = av.z; sA[akf*4+3][arow] = av.w; \
    *(float4*)&sB[bk][bn4*4] = bv; \
    __syncthreads(); \
    _Pragma("unroll") for (int kk = 0; kk < 8; kk++) { \
        float4 a0 = *(const float4*)&sA[kk][ty*8]; \
        float4 a1 = *(const float4*)&sA[kk][ty*8+4]; \
        float4 b0 = *(const float4*)&sB[kk][tx*8]; \
        float4 b1 = *(const float4*)&sB[kk][tx*8+4]; \
        float ar[8] = {a0.x,a0.y,a0.z,a0.w,a1.x,a1.y,a1.z,a1.w}; \
        float br[8] = {b0.x,b0.y,b0.z,b0.w,b1.x,b1.y,b1.z,b1.w}; \
        _Pragma("unroll") for (int i = 0; i < 8; i++) \
        _Pragma("unroll") for (int j = 0; j < 8; j++) acc[i][j] += ar[i]*br[j]; \
    } }

__global__ __launch_bounds__(256) void xproj_kernel(const float* __restrict__ TI,
                                                    const float* __restrict__ W,
                                                    const float* __restrict__ bias) {
    GEMM_DECLS
    const int t = blockIdx.y, n0 = blockIdx.x * 128;
    const float* Ab = TI + (size_t)arow * (TI_T * UU) + (size_t)t * UU + akf * 4;
    const float* Bb = W + (size_t)bk * GG + n0 + bn4 * 4;
    for (int k0 = 0; k0 < UU; k0 += 8)
        GEMM_STEP(*(const float4*)(Ab + k0), *(const float4*)(Bb + (size_t)k0 * GG));
    float4 q0 = *(const float4*)&bias[n0 + tx*8];
    float4 q1 = *(const float4*)&bias[n0 + tx*8 + 4];
    float bb[8] = {q0.x,q0.y,q0.z,q0.w,q1.x,q1.y,q1.z,q1.w};
#pragma unroll
    for (int i = 0; i < 8; i++) {
        float* op = g_xproj + ((size_t)t * BB + ty*8 + i) * GG + n0 + tx*8;
        *(float4*)op     = make_float4(acc[i][0]+bb[0], acc[i][1]+bb[1], acc[i][2]+bb[2], acc[i][3]+bb[3]);
        *(float4*)(op+4) = make_float4(acc[i][4]+bb[4], acc[i][5]+bb[5], acc[i][6]+bb[6], acc[i][7]+bb[7]);
    }
}

__global__ __launch_bounds__(256) void step_gemm(const float* __restrict__ Rk, int t) {
    GEMM_DECLS
    const int gc0 = blockIdx.x * 128, split = blockIdx.y;
    const float* h = g_h + (size_t)t * (BB * UU);
    const int ks = split * 64;
    for (int k0 = ks; k0 < ks + 64; k0 += 8)
        GEMM_STEP(*(const float4*)(h + (size_t)arow*UU + k0 + akf*4),
                  *(const float4*)(Rk + (size_t)(k0+bk)*GG + gc0 + bn4*4));
    float* zp = g_zpart + (size_t)split * (BB * GG) + gc0;
#pragma unroll
    for (int i = 0; i < 8; i++) {
        float* op = zp + (size_t)(ty*8 + i) * GG + tx*8;
        *(float4*)op     = make_float4(acc[i][0], acc[i][1], acc[i][2], acc[i][3]);
        *(float4*)(op+4) = make_float4(acc[i][4], acc[i][5], acc[i][6], acc[i][7]);
    }
}

__device__ __forceinline__ float sigm(float x) { return 1.f / (1.f + expf(-x)); }

__global__ void gate_kernel(int t) {
    int idx = blockIdx.x * blockDim.x + threadIdx.x;
    int b = idx >> 9, u = idx & 511;
    const float* xp = g_xproj + (size_t)t * (BB * GG) + (size_t)b * GG;
    float zi = xp[u], zf = xp[512+u], zg = xp[1024+u], zo = xp[1536+u];
#pragma unroll
    for (int s = 0; s < 8; s++) {
        const float* zp = g_zpart + (size_t)s * (BB * GG) + (size_t)b * GG;
        zi += zp[u]; zf += zp[512+u]; zg += zp[1024+u]; zo += zp[1536+u];
    }
    float c = g_c[idx];
    float cn = sigm(zf) * c + sigm(zi) * tanhf(zg);
    g_c[idx] = cn;
    g_h[(size_t)(t+1) * (BB*UU) + idx] = sigm(zo) * tanhf(cn);
}

// Attention: block = (16 timesteps, one batch b). smem: sHT[512][20] | sSc[16][264] | sS1[16][260]
#define HPAD 20
#define SCP 264
#define S1P 260
#define ATTN_SMEM_BYTES (18624 * 4)

__global__ __launch_bounds__(256) void attn_kernel(const float* __restrict__ SRC) {
    extern __shared__ float sm[];
    float* sHT = sm;
    float* sSc = sm + 10240;
    float* sS1 = sm + 14464;
    const int tid = threadIdx.x;
    const int t0 = blockIdx.x * 16, b = blockIdx.y;
    const float* src = SRC + (size_t)b * (SSN * UU);
#pragma unroll
    for (int i = 0; i < 8; i++) {
        int f4 = tid + i*256, tt = f4 >> 7, kq = f4 & 127;
        float4 v = *(const float4*)&g_h[(size_t)(t0+tt+1)*(BB*UU) + (size_t)b*UU + kq*4];
        sHT[(kq*4+0)*HPAD+tt] = v.x; sHT[(kq*4+1)*HPAD+tt] = v.y;
        sHT[(kq*4+2)*HPAD+tt] = v.z; sHT[(kq*4+3)*HPAD+tt] = v.w;
    }
    __syncthreads();
    const int tg = tid >> 6, sg = tid & 63;
    float acc[4][4];
#pragma unroll
    for (int i = 0; i < 4; i++)
#pragma unroll
        for (int j = 0; j < 4; j++) acc[i][j] = 0.f;
    for (int k0 = 0; k0 < UU; k0 += 16) {
#pragma unroll
        for (int i = 0; i < 4; i++) {
            int f4 = tid + i*256, s = f4 >> 2, kq = f4 & 3;
            float4 v = *(const float4*)&src[(size_t)s*UU + k0 + kq*4];
            sS1[(kq*4+0)*S1P+s] = v.x; sS1[(kq*4+1)*S1P+s] = v.y;
            sS1[(kq*4+2)*S1P+s] = v.z; sS1[(kq*4+3)*S1P+s] = v.w;
        }
        __syncthreads();
#pragma unroll
        for (int kk = 0; kk < 16; kk++) {
            float4 hv = *(const float4*)&sHT[(k0+kk)*HPAD + tg*4];
            float4 sv = *(const float4*)&sS1[kk*S1P + sg*4];
            float hr[4] = {hv.x,hv.y,hv.z,hv.w};
            float sr[4] = {sv.x,sv.y,sv.z,sv.w};
#pragma unroll
            for (int i = 0; i < 4; i++)
#pragma unroll
                for (int j = 0; j < 4; j++) acc[i][j] += hr[i]*sr[j];
        }
        __syncthreads();
    }
#pragma unroll
    for (int i = 0; i < 4; i++)
#pragma unroll
        for (int j = 0; j < 4; j++) sSc[(tg*4+i)*SCP + sg*4+j] = acc[i][j];
    __syncthreads();
    {
        const int w = tid >> 5, lane = tid & 31;
#pragma unroll
        for (int rr = 0; rr < 2; rr++) {
            int row = w*2 + rr;
            float v[8], m = -1e30f;
#pragma unroll
            for (int q = 0; q < 8; q++) { v[q] = sSc[row*SCP + lane + q*32]; m = fmaxf(m, v[q]); }
#pragma unroll
            for (int o = 16; o > 0; o >>= 1) m = fmaxf(m, __shfl_xor_sync(0xffffffffu, m, o));
            float ssum = 0.f;
#pragma unroll
            for (int q = 0; q < 8; q++) { v[q] = expf(v[q] - m); ssum += v[q]; }
#pragma unroll
            for (int o = 16; o > 0; o >>= 1) ssum += __shfl_xor_sync(0xffffffffu, ssum, o);
            float inv = 1.f / ssum;
#pragma unroll
            for (int q = 0; q < 8; q++) sSc[row*SCP + lane + q*32] = v[q] * inv;
        }
    }
    __syncthreads();
    float* sSrc = sm;
    const int ug = tid & 63;
    float acc2[4][8];
#pragma unroll
    for (int i = 0; i < 4; i++)
#pragma unroll
        for (int j = 0; j < 8; j++) acc2[i][j] = 0.f;
    for (int s0 = 0; s0 < SSN; s0 += 16) {
        __syncthreads();
#pragma unroll
        for (int i = 0; i < 8; i++) {
            int f4 = tid + i*256, si = f4 >> 7, uq = f4 & 127;
            *(float4*)&sSrc[si*UU + uq*4] = *(const float4*)&src[(size_t)(s0+si)*UU + uq*4];
        }
        __syncthreads();
#pragma unroll
        for (int si = 0; si < 16; si++) {
            float ar[4];
#pragma unroll
            for (int i = 0; i < 4; i++) ar[i] = sSc[(tg*4+i)*SCP + s0 + si];
            float4 u0 = *(const float4*)&sSrc[si*UU + ug*8];
            float4 u1 = *(const float4*)&sSrc[si*UU + ug*8 + 4];
            float ur[8] = {u0.x,u0.y,u0.z,u0.w,u1.x,u1.y,u1.z,u1.w};
#pragma unroll
            for (int i = 0; i < 4; i++)
#pragma unroll
                for (int j = 0; j < 8; j++) acc2[i][j] += ar[i]*ur[j];
        }
    }
#pragma unroll
    for (int i = 0; i < 4; i++) {
        float* wp = g_w + ((size_t)(t0 + tg*4 + i) * BB + b) * UU + ug*8;
        *(float4*)wp     = make_float4(acc2[i][0], acc2[i][1], acc2[i][2], acc2[i][3]);
        *(float4*)(wp+4) = make_float4(acc2[i][4], acc2[i][5], acc2[i][6], acc2[i][7]);
    }
}

__global__ __launch_bounds__(256) void final_gemm(const float* __restrict__ Wa,
                                                  float* __restrict__ out) {
    GEMM_DECLS
    const int t = blockIdx.y, n0 = blockIdx.x * 128;
    for (int k0 = 0; k0 < 1024; k0 += 8) {
        const float* Ab = (k0 < 512)
            ? (g_h + (size_t)(t+1)*(BB*UU) + k0)
            : (g_w + (size_t)t*(BB*UU) + (k0 - 512));
        GEMM_STEP(*(const float4*)(Ab + (size_t)arow*UU + akf*4),
                  *(const float4*)(Wa + (size_t)(k0+bk)*UU + n0 + bn4*4));
    }
#pragma unroll
    for (int i = 0; i < 8; i++) {
        int r = ty*8 + i;
        float* op = out + (size_t)r * (TTN*UU) + (size_t)t * UU + n0 + tx*8;
        *(float4*)op     = make_float4(tanhf(acc[i][0]), tanhf(acc[i][1]), tanhf(acc[i][2]), tanhf(acc[i][3]));
        *(float4*)(op+4) = make_float4(tanhf(acc[i][4]), tanhf(acc[i][5]), tanhf(acc[i][6]), tanhf(acc[i][7]));
    }
}

extern "C" void kernel_launch(void* const* d_in, const int* in_sizes, int n_in,
                              void* d_out, int out_size) {
    (void)in_sizes; (void)n_in; (void)out_size;
    const float* h0   = (const float*)d_in[0];
    const float* c0   = (const float*)d_in[1];
    const float* src  = (const float*)d_in[2];
    const float* ti   = (const float*)d_in[3];
    const float* W    = (const float*)d_in[4];
    const float* Rk   = (const float*)d_in[5];
    const float* bias = (const float*)d_in[6];
    const float* Wa   = (const float*)d_in[7];
    float* out = (float*)d_out;

    cudaFuncSetAttribute(attn_kernel, cudaFuncAttributeMaxDynamicSharedMemorySize,
                         ATTN_SMEM_BYTES);

    init_kernel<<<256, 256>>>(h0, c0);
    xproj_kernel<<<dim3(16, 256), 256>>>(ti, W, bias);
    for (int t = 0; t < TTN; t++) {
        step_gemm<<<dim3(16, 8), 256>>>(Rk, t);
        gate_kernel<<<256, 256>>>(t);
    }
    attn_kernel<<<dim3(16, 128), 256, ATTN_SMEM_BYTES>>>(src);
    final_gemm<<<dim3(4, 256), 256>>>(Wa, out);
}